// round 14
// baseline (speedup 1.0000x reference)
#include <cuda_runtime.h>
#include <cuda_fp16.h>
#include <math.h>
#include <stdint.h>

#define B_ 32
#define C_ 512
#define S_ 1024
#define K_ 256
#define M_ 256

// ---------------- scratch (no allocs allowed) ----------------
__device__ float g_hproj[B_ * K_];
__device__ float g_a2[B_ * S_];
__device__ __half g_Wh[K_ * C_];
__device__ int   g_cnt[B_];

__device__ __forceinline__ uint32_t smem_u32(const void* p) {
    uint32_t a;
    asm("{ .reg .u64 t; cvta.to.shared.u64 t, %1; cvt.u32.u64 %0, t; }" : "=r"(a) : "l"(p));
    return a;
}

// ---------------- kernel 1: fused prep (128 blocks, ONE wave) ----------------
// Every block: (a) wconv slice (4 elems/thread), (b) a2-zero slice (1/thread),
// (c) hproj for (b = bid>>2, kg = bid&3) — all loads issued up-front.
__global__ __launch_bounds__(256)
void prep_kernel(const float* __restrict__ Wc,
                 const float* __restrict__ h,
                 const float* __restrict__ Wl,
                 const float* __restrict__ bl) {
    const int bid = blockIdx.x;        // 0..127
    const int tid = threadIdx.x;
    const int b    = bid >> 2;
    const int kg   = bid & 3;
    const int wid  = tid >> 5;
    const int lane = tid & 31;

    __shared__ float hs[M_];

    // ---- issue all independent loads first (max MLP) ----
    // wconv slice: 128*256*4 = 131072 = K_*C_
    const int i4 = (bid * 256 + tid) * 4;
    float4 wv = *(const float4*)(Wc + i4);
    // h for this batch
    hs[tid] = h[b * M_ + tid];
    // a2 zero: 128*256 = 32768 = B_*S_
    g_a2[bid * 256 + tid] = 0.0f;
    if (bid == 0 && tid < B_) g_cnt[tid] = 0;

    // wconv convert+store (no sync needed; independent of hs)
    __half2 p0 = __floats2half2_rn(wv.x, wv.y);
    __half2 p1 = __floats2half2_rn(wv.z, wv.w);
    uint2 o;
    o.x = *(uint32_t*)&p0; o.y = *(uint32_t*)&p1;
    *(uint2*)(g_Wh + i4) = o;

    __syncthreads();

    // ---- hproj: warp computes 8 k's with 8 independent accumulators ----
    float hv[8];
#pragma unroll
    for (int j = 0; j < 8; j++) hv[j] = hs[lane + 32 * j];

    const int kbase = kg * 64 + wid * 8;
    const float* base = Wl + (size_t)kbase * M_;
    float sk[8];
#pragma unroll
    for (int q = 0; q < 8; q++) sk[q] = 0.f;
#pragma unroll
    for (int q = 0; q < 8; q++) {
        const float* wrow = base + (size_t)q * M_;
#pragma unroll
        for (int j = 0; j < 8; j++)
            sk[q] += hv[j] * wrow[lane + 32 * j];
    }
#pragma unroll
    for (int q = 0; q < 8; q++)
#pragma unroll
        for (int m = 16; m > 0; m >>= 1)
            sk[q] += __shfl_xor_sync(0xffffffffu, sk[q], m);
    if (lane == 0) {
#pragma unroll
        for (int q = 0; q < 8; q++)
            g_hproj[b * K_ + kbase + q] = sk[q] + bl[kbase + q];
    }
}

// ---------------- kernel 2: mma.sync fused logits + ticket softmax -----------
#define CHUNK_C 64
#define N_CHUNKS (C_ / CHUNK_C)    // 8

#define PA_ELEM 72                  // W tile pitch in fp16 elems (144B)
#define OFF_A 0
#define PX_WORDS 136                // x tile pitch in u32 words (544B)
#define OFF_X 18432                 // 128 rows * 144B
#define STAGE_BYTES 35840           // + 32*544
#define DYN_BYTES (2 * STAGE_BYTES)

extern __shared__ __align__(16) char dyn_smem[];

__device__ __forceinline__ uint32_t pack_half2(float lo, float hi) {
    __half2 p = __floats2half2_rn(lo, hi);
    return *(uint32_t*)&p;
}

__device__ __forceinline__ void mma16816(float* d, uint32_t a0, uint32_t a1,
                                         uint32_t a2, uint32_t a3,
                                         uint32_t b0, uint32_t b1) {
    asm volatile(
        "mma.sync.aligned.m16n8k16.row.col.f32.f16.f16.f32 "
        "{%0,%1,%2,%3}, {%4,%5,%6,%7}, {%8,%9}, {%0,%1,%2,%3};"
        : "+f"(d[0]), "+f"(d[1]), "+f"(d[2]), "+f"(d[3])
        : "r"(a0), "r"(a1), "r"(a2), "r"(a3), "r"(b0), "r"(b1));
}

__device__ __forceinline__ void ldmatrix_x4(uint32_t& r0, uint32_t& r1,
                                            uint32_t& r2, uint32_t& r3,
                                            uint32_t addr) {
    asm volatile("ldmatrix.sync.aligned.m8n8.x4.shared.b16 {%0,%1,%2,%3}, [%4];"
                 : "=r"(r0), "=r"(r1), "=r"(r2), "=r"(r3) : "r"(addr));
}

__device__ __forceinline__ void fill_W_async(char* st, const __half* __restrict__ Wsrc,
                                             int c0, int tid) {
#pragma unroll
    for (int it = 0; it < 4; it++) {
        const int idx = tid + it * 256;
        const int k   = idx >> 3;
        const int seg = idx & 7;
        const uint32_t dst = smem_u32(st + OFF_A + k * 144 + seg * 16);
        const __half* src = Wsrc + (size_t)k * C_ + c0 + seg * 8;
        asm volatile("cp.async.cg.shared.global [%0], [%1], 16;" :: "r"(dst), "l"(src));
    }
    asm volatile("cp.async.commit_group;" ::: "memory");
}

__device__ __forceinline__ void fill_X(char* st, const float* __restrict__ xb,
                                       int c0, int tid) {
    const int lane = tid & 31;
    const int w    = tid >> 5;
#pragma unroll
    for (int cc = 0; cc < 4; cc++) {
        const int c2 = w + cc * 8;         // 0..31
        const float* r0 = xb + (size_t)(c0 + 2 * c2) * S_;
        const float* r1 = r0 + S_;
        float4 v0 = *(const float4*)(r0 + lane * 4);
        float4 v1 = *(const float4*)(r1 + lane * 4);
        uint4 ph;
        ph.x = pack_half2(v0.x, v1.x);
        ph.y = pack_half2(v0.y, v1.y);
        ph.z = pack_half2(v0.z, v1.z);
        ph.w = pack_half2(v0.w, v1.w);
        *(uint4*)(st + OFF_X + c2 * 544 + lane * 16) = ph;
    }
}

__global__ __launch_bounds__(256, 2)
void attn_logits_mma(const float* __restrict__ x,
                     const float* __restrict__ Wattn,
                     float* __restrict__ a3_out) {
    const int kh    = blockIdx.x;      // 0..1 (128-k half)
    const int stile = blockIdx.y;      // 0..7
    const int b     = blockIdx.z;      // 0..31
    const int tid   = threadIdx.x;
    const int wid   = tid >> 5;
    const int lane  = tid & 31;
    const int g     = lane >> 2;
    const int t     = lane & 3;
    const int kq    = wid >> 2;
    const int ws    = wid & 3;

    __shared__ float a2s[128];
    __shared__ float hp_s[128];
    __shared__ float wa_s[128];
    __shared__ float red8[8];
    __shared__ int   s_tick;

    char* tiles = dyn_smem;
    const uint32_t tiles_u32 = smem_u32(tiles);
    const float* xb    = x + (size_t)b * C_ * S_ + (size_t)stile * 128;
    const __half* Wsrc = g_Wh + (size_t)kh * 128 * C_;

    const uint32_t lrow = lane & 15;
    const uint32_t lcol = (lane >> 4) * 16;   // bytes

    fill_W_async(tiles, Wsrc, 0, tid);
    fill_X(tiles, xb, 0, tid);
    if (tid < 128) {
        hp_s[tid] = g_hproj[b * K_ + kh * 128 + tid];
        wa_s[tid] = Wattn[kh * 128 + tid];
        a2s[tid]  = 0.0f;
    }
    asm volatile("cp.async.wait_group 0;" ::: "memory");
    __syncthreads();

    float acc[4][4][4];
#pragma unroll
    for (int i = 0; i < 4; i++)
#pragma unroll
        for (int j = 0; j < 4; j++)
#pragma unroll
            for (int r = 0; r < 4; r++) acc[i][j][r] = 0.0f;

    for (int ch = 0; ch < N_CHUNKS; ch++) {
        const int p = ch & 1;
        if (ch + 1 < N_CHUNKS) {
            fill_W_async(tiles + (p ^ 1) * STAGE_BYTES, Wsrc, (ch + 1) * CHUNK_C, tid);
            fill_X(tiles + (p ^ 1) * STAGE_BYTES, xb, (ch + 1) * CHUNK_C, tid);
        }

        const char* st = tiles + p * STAGE_BYTES;
        const uint32_t Ah_u32 = tiles_u32 + p * STAGE_BYTES + OFF_A;
        const uint32_t* Xh = (const uint32_t*)(st + OFF_X);

#pragma unroll
        for (int kt = 0; kt < 4; kt++) {
            uint32_t bh[4][2];
#pragma unroll
            for (int j = 0; j < 4; j++) {
                const int s = ws * 32 + j * 8 + g;
                bh[j][0] = Xh[(kt * 8 + t)     * PX_WORDS + s];
                bh[j][1] = Xh[(kt * 8 + t + 4) * PX_WORDS + s];
            }
#pragma unroll
            for (int i = 0; i < 4; i++) {
                const int k0 = kq * 64 + i * 16;
                const uint32_t a_addr =
                    Ah_u32 + ((k0 + lrow) * PA_ELEM + kt * 16) * 2 + lcol;
                uint32_t ah0, ah1, ah2, ah3;
                ldmatrix_x4(ah0, ah1, ah2, ah3, a_addr);
#pragma unroll
                for (int j = 0; j < 4; j++)
                    mma16816(acc[i][j], ah0, ah1, ah2, ah3, bh[j][0], bh[j][1]);
            }
        }
        if (ch + 1 < N_CHUNKS)
            asm volatile("cp.async.wait_group 0;" ::: "memory");
        __syncthreads();
    }

    // ---- epilogue: tanh + W_attn partial reduction over this k-half ----
    float part[4][2];
#pragma unroll
    for (int j = 0; j < 4; j++) { part[j][0] = 0.0f; part[j][1] = 0.0f; }

#pragma unroll
    for (int i = 0; i < 4; i++)
#pragma unroll
        for (int half = 0; half < 2; half++) {
            const int kl = kq * 64 + i * 16 + half * 8 + g;
            const float hp = hp_s[kl];
            const float wa = wa_s[kl];
#pragma unroll
            for (int j = 0; j < 4; j++) {
#pragma unroll
                for (int pc = 0; pc < 2; pc++) {
                    const float y = acc[i][j][half * 2 + pc];
                    part[j][pc] += tanhf(y + hp) * wa;
                }
            }
        }

#pragma unroll
    for (int m = 4; m <= 16; m <<= 1)
#pragma unroll
        for (int j = 0; j < 4; j++) {
            part[j][0] += __shfl_xor_sync(0xffffffffu, part[j][0], m);
            part[j][1] += __shfl_xor_sync(0xffffffffu, part[j][1], m);
        }

    if (lane < 4) {
#pragma unroll
        for (int j = 0; j < 4; j++) {
            atomicAdd(&a2s[ws * 32 + j * 8 + 2 * lane + 0], part[j][0]);
            atomicAdd(&a2s[ws * 32 + j * 8 + 2 * lane + 1], part[j][1]);
        }
    }
    __syncthreads();
    if (tid < 128)
        atomicAdd(&g_a2[b * S_ + stile * 128 + tid], a2s[tid]);

    // ---- ticket softmax: last of the 16 CTAs for this batch ----
    __threadfence();
    if (tid == 0) s_tick = atomicAdd(&g_cnt[b], 1);
    __syncthreads();
    if (s_tick == 15) {
        __threadfence();
        float v[4];
#pragma unroll
        for (int i = 0; i < 4; i++)
            v[i] = __ldcg(&g_a2[b * S_ + tid + i * 256]);
        float mx = fmaxf(fmaxf(v[0], v[1]), fmaxf(v[2], v[3]));
#pragma unroll
        for (int m = 16; m > 0; m >>= 1)
            mx = fmaxf(mx, __shfl_xor_sync(0xffffffffu, mx, m));
        if (lane == 0) red8[wid] = mx;
        __syncthreads();
        mx = red8[0];
#pragma unroll
        for (int w = 1; w < 8; w++) mx = fmaxf(mx, red8[w]);

        float s = 0.0f;
#pragma unroll
        for (int i = 0; i < 4; i++) { v[i] = expf(v[i] - mx); s += v[i]; }
#pragma unroll
        for (int m = 16; m > 0; m >>= 1)
            s += __shfl_xor_sync(0xffffffffu, s, m);
        __syncthreads();
        if (lane == 0) red8[wid] = s;
        __syncthreads();
        s = red8[0];
#pragma unroll
        for (int w = 1; w < 8; w++) s += red8[w];
        const float inv = 1.0f / s;
#pragma unroll
        for (int i = 0; i < 4; i++)
            a3_out[b * S_ + tid + i * 256] = v[i] * inv;
        if (tid == 0) g_cnt[b] = 0;
    }
}

// ---------------- kernel 3: context (R10 version — best measured) ------------
__global__ __launch_bounds__(256)
void context_kernel(const float* __restrict__ x,
                    const float* __restrict__ a3,
                    float* __restrict__ ctx) {
    const int b  = blockIdx.x;
    const int cg = blockIdx.y;                 // 64 groups of 8 channels
    const int w    = threadIdx.x >> 5;
    const int lane = threadIdx.x & 31;
    const int c = cg * 8 + w;
    const float4* xr = (const float4*)(x + ((size_t)b * C_ + c) * S_);
    const float4* ar = (const float4*)(a3 + (size_t)b * S_);
    float s0 = 0, s1 = 0, s2 = 0, s3 = 0;
#pragma unroll
    for (int it = 0; it < 8; it++) {
        float4 xv = __ldcs(&xr[lane + it * 32]);
        float4 av = __ldg(&ar[lane + it * 32]);
        s0 += xv.x * av.x; s1 += xv.y * av.y;
        s2 += xv.z * av.z; s3 += xv.w * av.w;
    }
    float s = (s0 + s1) + (s2 + s3);
#pragma unroll
    for (int off = 16; off > 0; off >>= 1)
        s += __shfl_down_sync(0xffffffffu, s, off);
    if (lane == 0) ctx[b * C_ + c] = s;
}

// ---------------- launch ----------------
extern "C" void kernel_launch(void* const* d_in, const int* in_sizes, int n_in,
                              void* d_out, int out_size) {
    const float* x  = (const float*)d_in[0];
    const float* h  = (const float*)d_in[1];
    const float* Wc = (const float*)d_in[2];
    const float* Wl = (const float*)d_in[3];
    const float* bl = (const float*)d_in[4];
    const float* Wa = (const float*)d_in[5];

    float* out = (float*)d_out;
    float* a3  = out;
    float* ctx = out + B_ * S_;

    cudaFuncSetAttribute(attn_logits_mma,
                         cudaFuncAttributeMaxDynamicSharedMemorySize, DYN_BYTES);

    prep_kernel<<<128, 256>>>(Wc, h, Wl, bl);
    attn_logits_mma<<<dim3(2, 8, B_), 256, DYN_BYTES>>>(x, Wa, a3);
    context_kernel<<<dim3(B_, 64), 256>>>(x, a3, ctx);
}